// round 4
// baseline (speedup 1.0000x reference)
#include <cuda_runtime.h>
#include <cuda_bf16.h>
#include <math.h>

// ---- problem constants ----
#define NPTS   4096
#define NVIEW  6
#define SDIM   128
#define KTOP   5
#define RADIUS 0.01f
#define R2F    (RADIUS*RADIUS)
#define ZNEARF 0.01f
#define ZFARF  100.0f
#define NPIX   (NVIEW*SDIM*SDIM)   // 98304
#define MSLOT  32
#define TPB    256

// ---- scratch (static __device__; zero-initialized at module load; the
// composite phase resets g_cnt after reading, so every invocation / graph
// replay starts from zeroed counters with no memset node) ----
__device__ int   g_cnt[NPIX];
__device__ float g_z[NPIX*MSLOT];
__device__ float g_w[NPIX*MSLOT];
__device__ float g_c[NPIX*MSLOT];

// ---- grid barrier state (generation grows monotonically across replays;
// only compared for equality, so unsigned wrap is harmless) ----
__device__ unsigned g_arrive = 0;
__device__ volatile unsigned g_gen = 0;

struct Cams {
    float R[NVIEW][9];   // row-major, columns are x,y,z camera basis
    float T[NVIEW][3];
};

__device__ __forceinline__ void grid_barrier() {
    __syncthreads();
    if (threadIdx.x == 0) {
        __threadfence();
        unsigned gen = g_gen;
        if (atomicAdd(&g_arrive, 1) == gridDim.x - 1) {
            g_arrive = 0;          // reset BEFORE bumping generation
            __threadfence();
            g_gen = gen + 1;       // release all waiters
        } else {
            while (g_gen == gen) { __nanosleep(32); }
        }
        __threadfence();
    }
    __syncthreads();
}

__global__ void __launch_bounds__(TPB, 1)
fused_render_kernel(const float* __restrict__ pcd,
                    const float* __restrict__ ic,
                    const float* __restrict__ dp,
                    float* __restrict__ out,
                    Cams cams) {
    int tid = blockIdx.x * TPB + threadIdx.x;

    // ================= phase A: colors + scatter =================
    if (tid < NPTS) {
        float col = 1.0f / (1.0f + __expf(-(ic[tid] + dp[tid])));
        out[(size_t)NPIX * 3 + tid] = col;   // colors_ tail of the output

        float p0 = pcd[3*tid+0], p1 = pcd[3*tid+1], p2 = pcd[3*tid+2];

        #pragma unroll
        for (int v = 0; v < NVIEW; v++) {
            const float* R = cams.R[v];
            const float* T = cams.T[v];
            float px = p0*R[0] + p1*R[3] + p2*R[6] + T[0];
            float py = p0*R[1] + p1*R[4] + p2*R[7] + T[1];
            float pz = p0*R[2] + p1*R[5] + p2*R[8] + T[2];
            if (!(pz > ZNEARF && pz < ZFARF)) continue;

            // pixel center coord (col j / row r): (S-1-2j)/S.
            // candidate band |t-j| < S*R/2 = 0.64 (0.66 slack; exact test below)
            float tx = 0.5f * ((float)(SDIM-1) - (float)SDIM * px);
            float ty = 0.5f * ((float)(SDIM-1) - (float)SDIM * py);
            int jlo = (int)ceilf (tx - 0.66f); if (jlo < 0) jlo = 0;
            int jhi = (int)floorf(tx + 0.66f); if (jhi > SDIM-1) jhi = SDIM-1;
            int ilo = (int)ceilf (ty - 0.66f); if (ilo < 0) ilo = 0;
            int ihi = (int)floorf(ty + 0.66f); if (ihi > SDIM-1) ihi = SDIM-1;

            for (int r = ilo; r <= ihi; r++) {
                float dy = (float)(SDIM-1-2*r) * (1.0f/(float)SDIM) - py;
                float dy2 = dy * dy;
                for (int c = jlo; c <= jhi; c++) {
                    float dx = (float)(SDIM-1-2*c) * (1.0f/(float)SDIM) - px;
                    float d2 = dx*dx + dy2;
                    if (d2 < R2F) {
                        int pix = (v*SDIM + r)*SDIM + c;
                        int n = atomicAdd(&g_cnt[pix], 1);
                        if (n < MSLOT) {
                            g_z[pix*MSLOT + n] = pz;
                            g_w[pix*MSLOT + n] = 1.0f - d2 * (1.0f/R2F);
                            g_c[pix*MSLOT + n] = col;
                        }
                    }
                }
            }
        }
    }

    // scatter writes -> visible to all blocks before composite
    grid_barrier();

    // ============ phase B: composite (4 pixels/thread, float4 stores) ============
    if (tid < NPIX/4) {
        float vals[12];
        #pragma unroll
        for (int s = 0; s < 4; s++) {
            int pix = 4*tid + s;
            int n = g_cnt[pix];
            g_cnt[pix] = 0;                  // reset for the next replay
            if (n > MSLOT) n = MSLOT;

            float acc = 0.0f, trans = 1.0f;
            unsigned used = 0u;
            int kmax = (n < KTOP) ? n : KTOP;
            for (int k = 0; k < kmax; k++) {
                float bz = 3.0e38f; int bi = 0;
                for (int e = 0; e < n; e++) {
                    if (used & (1u << e)) continue;
                    float z = g_z[pix*MSLOT + e];
                    if (z < bz) { bz = z; bi = e; }
                }
                used |= (1u << bi);
                float w = g_w[pix*MSLOT + bi];
                acc  += w * trans * g_c[pix*MSLOT + bi];
                trans *= (1.0f - w);
            }
            vals[3*s+0] = acc; vals[3*s+1] = acc; vals[3*s+2] = acc;
        }
        float4* o = reinterpret_cast<float4*>(out + (size_t)tid * 12);
        o[0] = make_float4(vals[0], vals[1], vals[2],  vals[3]);
        o[1] = make_float4(vals[4], vals[5], vals[6],  vals[7]);
        o[2] = make_float4(vals[8], vals[9], vals[10], vals[11]);
    }
}

// ---- host: replicate PyTorch3D look_at_view_transform ----
static void compute_cams(Cams& cams) {
    const double views[NVIEW] = {45.0, 90.0, 135.0, 225.0, 270.0, 315.0};
    const double elev = 15.0 * M_PI / 180.0;
    const double dist = 1.5;
    for (int v = 0; v < NVIEW; v++) {
        double az = views[v] * M_PI / 180.0;
        double C[3] = { dist*cos(elev)*sin(az), dist*sin(elev), dist*cos(elev)*cos(az) };
        double z[3] = { -C[0]/dist, -C[1]/dist, -C[2]/dist };
        double x[3] = { z[2], 0.0, -z[0] };
        double xn = sqrt(x[0]*x[0] + x[1]*x[1] + x[2]*x[2]);
        x[0]/=xn; x[1]/=xn; x[2]/=xn;
        double y[3] = { z[1]*x[2]-z[2]*x[1], z[2]*x[0]-z[0]*x[2], z[0]*x[1]-z[1]*x[0] };
        double yn = sqrt(y[0]*y[0] + y[1]*y[1] + y[2]*y[2]);
        y[0]/=yn; y[1]/=yn; y[2]/=yn;
        for (int r = 0; r < 3; r++) {
            cams.R[v][r*3+0] = (float)x[r];
            cams.R[v][r*3+1] = (float)y[r];
            cams.R[v][r*3+2] = (float)z[r];
        }
        cams.T[v][0] = (float)(-(C[0]*x[0] + C[1]*x[1] + C[2]*x[2]));
        cams.T[v][1] = (float)(-(C[0]*y[0] + C[1]*y[1] + C[2]*y[2]));
        cams.T[v][2] = (float)(-(C[0]*z[0] + C[1]*z[1] + C[2]*z[2]));
    }
}

extern "C" void kernel_launch(void* const* d_in, const int* in_sizes, int n_in,
                              void* d_out, int out_size) {
    const float* pcd = (const float*)d_in[0];
    const float* ic  = (const float*)d_in[1];
    const float* dp  = (const float*)d_in[2];
    float* out = (float*)d_out;

    Cams cams;
    compute_cams(cams);

    // One block per SM: co-residency guaranteed (0 smem, low regs, 256 thr),
    // so the software grid barrier cannot deadlock. NPIX/4 = 24576 quad tasks
    // fit in one pass for any grid >= 96 blocks.
    int nsm = 148;
    cudaDeviceGetAttribute(&nsm, cudaDevAttrMultiProcessorCount, 0);

    fused_render_kernel<<<nsm, TPB>>>(pcd, ic, dp, out, cams);
}

// round 5
// speedup vs baseline: 1.4171x; 1.4171x over previous
#include <cuda_runtime.h>
#include <cuda_bf16.h>
#include <math.h>

// ---- problem constants ----
#define NPTS   4096
#define NVIEW  6
#define SDIM   128
#define KTOP   5
#define RADIUS 0.01f
#define R2F    (RADIUS*RADIUS)
#define ZNEARF 0.01f
#define ZFARF  100.0f
#define NPIX   (NVIEW*SDIM*SDIM)   // 98304
#define MSLOT  32
#define TPB    256

// ---- scratch (static __device__; zero-initialized at module load; the
// composite kernel resets g_cnt after reading it, so every invocation /
// graph replay starts from zeroed counters without a memset node) ----
__device__ int   g_cnt[NPIX];
__device__ float g_z[NPIX*MSLOT];
__device__ float g_w[NPIX*MSLOT];
__device__ float g_c[NPIX*MSLOT];

struct Cams {
    float R[NVIEW][9];   // row-major, columns are x,y,z camera basis
    float T[NVIEW][3];
};

// ---- kernel 1: one thread per (point, view); sigmoid fused in ----
__global__ void __launch_bounds__(TPB)
scatter_kernel(const float* __restrict__ pcd,
               const float* __restrict__ ic,
               const float* __restrict__ dp,
               float* __restrict__ out_tail,
               Cams cams) {
    int tid = blockIdx.x * TPB + threadIdx.x;
    if (tid >= NPTS * NVIEW) return;
    int i = tid & (NPTS - 1);      // point index (coalesced within a view group)
    int v = tid >> 12;             // view index (NPTS = 4096 = 2^12)

    float col = 1.0f / (1.0f + __expf(-(ic[i] + dp[i])));
    if (v == 0) out_tail[i] = col;             // colors_ tail of the output

    float p0 = pcd[3*i+0], p1 = pcd[3*i+1], p2 = pcd[3*i+2];
    const float* R = cams.R[v];
    const float* T = cams.T[v];
    float px = p0*R[0] + p1*R[3] + p2*R[6] + T[0];
    float py = p0*R[1] + p1*R[4] + p2*R[7] + T[1];
    float pz = p0*R[2] + p1*R[5] + p2*R[8] + T[2];
    if (!(pz > ZNEARF && pz < ZFARF)) return;

    // pixel center coord (col j / row r): (S-1-2j)/S.
    // candidate band |t-j| < S*R/2 = 0.64 (0.66 slack; exact d2<R2 test below)
    float tx = 0.5f * ((float)(SDIM-1) - (float)SDIM * px);
    float ty = 0.5f * ((float)(SDIM-1) - (float)SDIM * py);
    int jlo = (int)ceilf (tx - 0.66f); if (jlo < 0) jlo = 0;
    int jhi = (int)floorf(tx + 0.66f); if (jhi > SDIM-1) jhi = SDIM-1;
    int ilo = (int)ceilf (ty - 0.66f); if (ilo < 0) ilo = 0;
    int ihi = (int)floorf(ty + 0.66f); if (ihi > SDIM-1) ihi = SDIM-1;

    for (int r = ilo; r <= ihi; r++) {
        float dy = (float)(SDIM-1-2*r) * (1.0f/(float)SDIM) - py;
        float dy2 = dy * dy;
        for (int c = jlo; c <= jhi; c++) {
            float dx = (float)(SDIM-1-2*c) * (1.0f/(float)SDIM) - px;
            float d2 = dx*dx + dy2;
            if (d2 < R2F) {
                int pix = (v*SDIM + r)*SDIM + c;
                int n = atomicAdd(&g_cnt[pix], 1);
                if (n < MSLOT) {
                    g_z[pix*MSLOT + n] = pz;
                    g_w[pix*MSLOT + n] = 1.0f - d2 * (1.0f/R2F);
                    g_c[pix*MSLOT + n] = col;
                }
            }
        }
    }
}

// ---- kernel 2: 4 pixels/thread, K-select + alpha composite, float4 stores ----
__global__ void __launch_bounds__(TPB)
composite_kernel(float* __restrict__ out) {
    int tid = blockIdx.x * TPB + threadIdx.x;
    if (tid >= NPIX/4) return;

    float vals[12];
    #pragma unroll
    for (int s = 0; s < 4; s++) {
        int pix = 4*tid + s;
        int n = g_cnt[pix];
        g_cnt[pix] = 0;                  // leave counters zeroed for next replay
        if (n > MSLOT) n = MSLOT;

        float acc = 0.0f, trans = 1.0f;
        unsigned used = 0u;
        int kmax = (n < KTOP) ? n : KTOP;
        for (int k = 0; k < kmax; k++) {
            float bz = 3.0e38f; int bi = 0;
            for (int e = 0; e < n; e++) {
                if (used & (1u << e)) continue;
                float z = g_z[pix*MSLOT + e];
                if (z < bz) { bz = z; bi = e; }
            }
            used |= (1u << bi);
            float w = g_w[pix*MSLOT + bi];
            acc  += w * trans * g_c[pix*MSLOT + bi];
            trans *= (1.0f - w);
        }
        vals[3*s+0] = acc; vals[3*s+1] = acc; vals[3*s+2] = acc;
    }
    float4* o = reinterpret_cast<float4*>(out + (size_t)tid * 12);
    o[0] = make_float4(vals[0], vals[1], vals[2],  vals[3]);
    o[1] = make_float4(vals[4], vals[5], vals[6],  vals[7]);
    o[2] = make_float4(vals[8], vals[9], vals[10], vals[11]);
}

// ---- host: replicate PyTorch3D look_at_view_transform ----
static void compute_cams(Cams& cams) {
    const double views[NVIEW] = {45.0, 90.0, 135.0, 225.0, 270.0, 315.0};
    const double elev = 15.0 * M_PI / 180.0;
    const double dist = 1.5;
    for (int v = 0; v < NVIEW; v++) {
        double az = views[v] * M_PI / 180.0;
        double C[3] = { dist*cos(elev)*sin(az), dist*sin(elev), dist*cos(elev)*cos(az) };
        double z[3] = { -C[0]/dist, -C[1]/dist, -C[2]/dist };
        double x[3] = { z[2], 0.0, -z[0] };
        double xn = sqrt(x[0]*x[0] + x[1]*x[1] + x[2]*x[2]);
        x[0]/=xn; x[1]/=xn; x[2]/=xn;
        double y[3] = { z[1]*x[2]-z[2]*x[1], z[2]*x[0]-z[0]*x[2], z[0]*x[1]-z[1]*x[0] };
        double yn = sqrt(y[0]*y[0] + y[1]*y[1] + y[2]*y[2]);
        y[0]/=yn; y[1]/=yn; y[2]/=yn;
        for (int r = 0; r < 3; r++) {
            cams.R[v][r*3+0] = (float)x[r];
            cams.R[v][r*3+1] = (float)y[r];
            cams.R[v][r*3+2] = (float)z[r];
        }
        cams.T[v][0] = (float)(-(C[0]*x[0] + C[1]*x[1] + C[2]*x[2]));
        cams.T[v][1] = (float)(-(C[0]*y[0] + C[1]*y[1] + C[2]*y[2]));
        cams.T[v][2] = (float)(-(C[0]*z[0] + C[1]*z[1] + C[2]*z[2]));
    }
}

extern "C" void kernel_launch(void* const* d_in, const int* in_sizes, int n_in,
                              void* d_out, int out_size) {
    const float* pcd = (const float*)d_in[0];
    const float* ic  = (const float*)d_in[1];
    const float* dp  = (const float*)d_in[2];
    float* out = (float*)d_out;

    Cams cams;
    compute_cams(cams);

    scatter_kernel<<<(NPTS*NVIEW + TPB-1) / TPB, TPB>>>(pcd, ic, dp,
                                                        out + (size_t)NPIX*3, cams);
    composite_kernel<<<(NPIX/4 + TPB-1) / TPB, TPB>>>(out);
}

// round 6
// speedup vs baseline: 2.7775x; 1.9600x over previous
#include <cuda_runtime.h>
#include <cuda_bf16.h>
#include <math.h>

// ---- problem constants ----
#define NPTS   4096
#define NVIEW  6
#define SDIM   128
#define KTOP   5
#define RADIUS 0.01f
#define R2F    (RADIUS*RADIUS)
#define ZNEARF 0.01f
#define ZFARF  100.0f
#define NPIX   (NVIEW*SDIM*SDIM)   // 98304
#define MSLOT  16
#define TPB    256
#define BIGZ   3.0e38f

// ---- scratch (static __device__; zero-initialized at module load; the
// composite kernel resets g_cnt after reading it, so every invocation /
// graph replay starts from zeroed counters without a memset node) ----
__device__ int    g_cnt[NPIX];
__device__ float4 g_e[NPIX*MSLOT];   // (z, w, color, unused) per entry

struct Cams {
    float R[NVIEW][9];   // row-major, columns are x,y,z camera basis
    float T[NVIEW][3];
};

// ---- kernel 1: one thread per (point, view); sigmoid fused in ----
__global__ void __launch_bounds__(TPB)
scatter_kernel(const float* __restrict__ pcd,
               const float* __restrict__ ic,
               const float* __restrict__ dp,
               float* __restrict__ out_tail,
               Cams cams) {
    int tid = blockIdx.x * TPB + threadIdx.x;
    if (tid >= NPTS * NVIEW) return;
    int i = tid & (NPTS - 1);      // point index (coalesced within a view group)
    int v = tid >> 12;             // view index (NPTS = 4096 = 2^12)

    float col = 1.0f / (1.0f + __expf(-(ic[i] + dp[i])));
    if (v == 0) out_tail[i] = col;             // colors_ tail of the output

    float p0 = pcd[3*i+0], p1 = pcd[3*i+1], p2 = pcd[3*i+2];
    const float* R = cams.R[v];
    const float* T = cams.T[v];
    float px = p0*R[0] + p1*R[3] + p2*R[6] + T[0];
    float py = p0*R[1] + p1*R[4] + p2*R[7] + T[1];
    float pz = p0*R[2] + p1*R[5] + p2*R[8] + T[2];
    if (!(pz > ZNEARF && pz < ZFARF)) return;

    // pixel center coord (col j / row r): (S-1-2j)/S.
    // candidate band |t-j| < S*R/2 = 0.64 (0.66 slack; exact d2<R2 test below)
    float tx = 0.5f * ((float)(SDIM-1) - (float)SDIM * px);
    float ty = 0.5f * ((float)(SDIM-1) - (float)SDIM * py);
    int jlo = (int)ceilf (tx - 0.66f); if (jlo < 0) jlo = 0;
    int jhi = (int)floorf(tx + 0.66f); if (jhi > SDIM-1) jhi = SDIM-1;
    int ilo = (int)ceilf (ty - 0.66f); if (ilo < 0) ilo = 0;
    int ihi = (int)floorf(ty + 0.66f); if (ihi > SDIM-1) ihi = SDIM-1;

    for (int r = ilo; r <= ihi; r++) {
        float dy = (float)(SDIM-1-2*r) * (1.0f/(float)SDIM) - py;
        float dy2 = dy * dy;
        for (int c = jlo; c <= jhi; c++) {
            float dx = (float)(SDIM-1-2*c) * (1.0f/(float)SDIM) - px;
            float d2 = dx*dx + dy2;
            if (d2 < R2F) {
                int pix = (v*SDIM + r)*SDIM + c;
                int n = atomicAdd(&g_cnt[pix], 1);
                if (n < MSLOT) {
                    g_e[pix*MSLOT + n] =
                        make_float4(pz, 1.0f - d2 * (1.0f/R2F), col, 0.0f);
                }
            }
        }
    }
}

// ---- kernel 2: 1 thread/pixel; one-pass register top-K + alpha composite ----
__global__ void __launch_bounds__(TPB)
composite_kernel(float* __restrict__ out) {
    int pix = blockIdx.x * TPB + threadIdx.x;
    if (pix >= NPIX) return;

    int n = g_cnt[pix];
    g_cnt[pix] = 0;                      // leave counters zeroed for next replay
    if (n > MSLOT) n = MSLOT;

    float acc = 0.0f;
    if (n > 0) {
        // sorted-by-z register lists (ascending); branch-free insertion
        float bz[KTOP], bw[KTOP], bc[KTOP];
        #pragma unroll
        for (int k = 0; k < KTOP; k++) { bz[k] = BIGZ; bw[k] = 0.0f; bc[k] = 0.0f; }

        for (int e = 0; e < n; e++) {
            float4 ent = g_e[pix*MSLOT + e];
            float z = ent.x, w = ent.y, c = ent.z;
            #pragma unroll
            for (int k = 0; k < KTOP; k++) {
                bool sw = z < bz[k];
                float tz = bz[k], tw = bw[k], tc = bc[k];
                if (sw) { bz[k] = z; bw[k] = w; bc[k] = c; z = tz; w = tw; c = tc; }
            }
        }

        float trans = 1.0f;
        #pragma unroll
        for (int k = 0; k < KTOP; k++) {
            bool ok = bz[k] < BIGZ;
            float w = ok ? bw[k] : 0.0f;
            acc  += w * trans * bc[k];
            trans *= (1.0f - w);
        }
    }

    float* o = out + (size_t)pix * 3;
    o[0] = acc; o[1] = acc; o[2] = acc;
}

// ---- host: replicate PyTorch3D look_at_view_transform ----
static void compute_cams(Cams& cams) {
    const double views[NVIEW] = {45.0, 90.0, 135.0, 225.0, 270.0, 315.0};
    const double elev = 15.0 * M_PI / 180.0;
    const double dist = 1.5;
    for (int v = 0; v < NVIEW; v++) {
        double az = views[v] * M_PI / 180.0;
        double C[3] = { dist*cos(elev)*sin(az), dist*sin(elev), dist*cos(elev)*cos(az) };
        double z[3] = { -C[0]/dist, -C[1]/dist, -C[2]/dist };
        double x[3] = { z[2], 0.0, -z[0] };
        double xn = sqrt(x[0]*x[0] + x[1]*x[1] + x[2]*x[2]);
        x[0]/=xn; x[1]/=xn; x[2]/=xn;
        double y[3] = { z[1]*x[2]-z[2]*x[1], z[2]*x[0]-z[0]*x[2], z[0]*x[1]-z[1]*x[0] };
        double yn = sqrt(y[0]*y[0] + y[1]*y[1] + y[2]*y[2]);
        y[0]/=yn; y[1]/=yn; y[2]/=yn;
        for (int r = 0; r < 3; r++) {
            cams.R[v][r*3+0] = (float)x[r];
            cams.R[v][r*3+1] = (float)y[r];
            cams.R[v][r*3+2] = (float)z[r];
        }
        cams.T[v][0] = (float)(-(C[0]*x[0] + C[1]*x[1] + C[2]*x[2]));
        cams.T[v][1] = (float)(-(C[0]*y[0] + C[1]*y[1] + C[2]*y[2]));
        cams.T[v][2] = (float)(-(C[0]*z[0] + C[1]*z[1] + C[2]*z[2]));
    }
}

extern "C" void kernel_launch(void* const* d_in, const int* in_sizes, int n_in,
                              void* d_out, int out_size) {
    const float* pcd = (const float*)d_in[0];
    const float* ic  = (const float*)d_in[1];
    const float* dp  = (const float*)d_in[2];
    float* out = (float*)d_out;

    Cams cams;
    compute_cams(cams);

    scatter_kernel<<<(NPTS*NVIEW + TPB-1) / TPB, TPB>>>(pcd, ic, dp,
                                                        out + (size_t)NPIX*3, cams);
    composite_kernel<<<(NPIX + TPB-1) / TPB, TPB>>>(out);
}